// round 7
// baseline (speedup 1.0000x reference)
#include <cuda_runtime.h>
#include <stdint.h>

// Problem constants (fixed shapes from reference)
#define SS 8192      // seq len
#define KK 4096      // keep_k
#define DD 2048      // hidden dim

// Output layout (flat float32):
//   [0 .. 8388608)         pruned_hidden  [1,4096,2048]
//   [8388608 .. 8392704)   pruned_mask    [1,4096]
//   [8392704 .. 8396800)   idx            [1,4096]
//   [8396800 .. 75505664)  pruned_keys    [8,1,16,4096,128]
//   [75505664 ..142614528) pruned_values  [8,1,16,4096,128]
#define OFF_MASK   8388608
#define OFF_IDX    8392704
#define OFF_KEYS4  2099200LL    // /4 (float4 units)
#define OFF_VALS4  18876416LL

#define H4  2097152LL           // hidden float4 count
#define KV4 16777216LL          // keys float4 count
#define TOTAL4 (H4 + 2*KV4)     // 35,651,584  (divisible by 1024)

// block-region boundaries for gather (1024 float4 per block)
#define HBLK 2048               // H4/1024
#define KBLK 16384              // KV4/1024

__device__ int g_idx[KK];

__device__ __forceinline__ unsigned f2u(float f) {
    unsigned u = __float_as_uint(f);
    return u ^ ((u >> 31) ? 0xFFFFFFFFu : 0x80000000u);
}

// -------------------------------------------------------------------------
// Kernel 1: single block. 4-pass 256-bin histogram select of the K-th
// largest key with warp-aggregated (match_any) smem atomics, then a block
// prefix-scan in token order emits kept indices already sorted ascending.
// -------------------------------------------------------------------------
__global__ __launch_bounds__(1024, 1)
void topk_kernel(const float4* __restrict__ scores4,
                 const int*    __restrict__ attn_mask,
                 float*        __restrict__ out)
{
    cudaTriggerProgrammaticLaunchCompletion();

    __shared__ unsigned skey[SS];
    __shared__ unsigned hist[256];
    __shared__ unsigned warp_gt[32], warp_eq[32];
    __shared__ unsigned s_prefix, s_krem;

    const int tid  = threadIdx.x;
    const int lane = tid & 31;

    // vectorized load + order-preserving transform (2048 float4)
    #pragma unroll
    for (int j = 0; j < 2; ++j) {
        int i = tid + j * 1024;
        float4 v = scores4[i];
        skey[i * 4 + 0] = f2u(v.x);
        skey[i * 4 + 1] = f2u(v.y);
        skey[i * 4 + 2] = f2u(v.z);
        skey[i * 4 + 3] = f2u(v.w);
    }
    if (tid == 0) { s_prefix = 0u; s_krem = KK; }

    // ---- 4 passes of 8-bit histogram select (MSB first) ----
    #pragma unroll
    for (int pass = 0; pass < 4; ++pass) {
        const int shift = 24 - 8 * pass;
        if (tid < 256) hist[tid] = 0u;
        __syncthreads();
        const unsigned prefix = s_prefix;
        const unsigned maskhi = (pass == 0) ? 0u : (0xFFFFFFFFu << (shift + 8));
        #pragma unroll
        for (int j = 0; j < SS / 1024; ++j) {
            unsigned k   = skey[tid + j * 1024];
            bool     act = ((k & maskhi) == prefix);
            unsigned bin = act ? ((k >> shift) & 255u) : 0xFFFFFFFFu;
            // warp-aggregate: one atomic per distinct bin per warp
            unsigned peers  = __match_any_sync(0xFFFFFFFFu, bin);
            int      leader = __ffs(peers) - 1;
            if (act && lane == leader) atomicAdd(&hist[bin], (unsigned)__popc(peers));
        }
        __syncthreads();
        if (tid < 32) {
            unsigned local[8], lsum = 0;
            #pragma unroll
            for (int j = 0; j < 8; ++j) { local[j] = hist[255 - (tid * 8 + j)]; lsum += local[j]; }
            unsigned incl = lsum;
            #pragma unroll
            for (int o = 1; o < 32; o <<= 1) {
                unsigned t = __shfl_up_sync(0xffffffffu, incl, o);
                if (tid >= o) incl += t;
            }
            unsigned excl = incl - lsum;
            unsigned krem = s_krem;
            if (excl < krem && incl >= krem) {   // exactly one lane
                unsigned rem = krem - excl;
                #pragma unroll
                for (int j = 0; j < 8; ++j) {
                    if (local[j] >= rem) {
                        s_prefix = prefix | ((unsigned)(255 - (tid * 8 + j)) << shift);
                        s_krem = rem;
                        break;
                    }
                    rem -= local[j];
                }
            }
        }
        __syncthreads();
    }
    const unsigned T    = s_prefix;   // exact K-th largest key
    const unsigned need = s_krem;     // how many ==T entries to keep (lowest idx first)

    // ---- ordered emit via block prefix scan over (>,==) counts ----
    const int base = tid * 8;
    unsigned lg = 0, le = 0;
    #pragma unroll
    for (int j = 0; j < 8; ++j) {
        unsigned k = skey[base + j];
        lg += (k > T);
        le += (k == T);
    }
    unsigned eg = lg, ee = le;
    #pragma unroll
    for (int o = 1; o < 32; o <<= 1) {
        unsigned tg = __shfl_up_sync(0xffffffffu, eg, o);
        unsigned te = __shfl_up_sync(0xffffffffu, ee, o);
        if (lane >= o) { eg += tg; ee += te; }
    }
    if (lane == 31) { warp_gt[tid >> 5] = eg; warp_eq[tid >> 5] = ee; }
    __syncthreads();
    if (tid < 32) {
        unsigned g = warp_gt[tid], e = warp_eq[tid];
        #pragma unroll
        for (int o = 1; o < 32; o <<= 1) {
            unsigned tg = __shfl_up_sync(0xffffffffu, g, o);
            unsigned te = __shfl_up_sync(0xffffffffu, e, o);
            if (tid >= o) { g += tg; e += te; }
        }
        warp_gt[tid] = g; warp_eq[tid] = e;
    }
    __syncthreads();

    const int w = tid >> 5;
    unsigned gt_before = ((w == 0) ? 0u : warp_gt[w - 1]) + (eg - lg);
    unsigned eq_before = ((w == 0) ? 0u : warp_eq[w - 1]) + (ee - le);

    #pragma unroll
    for (int j = 0; j < 8; ++j) {
        const int i = base + j;
        unsigned k = skey[i];
        bool gt = (k > T);
        bool eq = (k == T);
        bool sel = gt || (eq && (eq_before < need));
        if (sel) {
            unsigned pos = gt_before + min(eq_before, need);
            g_idx[pos] = i;
            out[OFF_IDX  + pos] = (float)i;
            out[OFF_MASK + pos] = (float)attn_mask[i];
        }
        gt_before += gt ? 1u : 0u;
        eq_before += eq ? 1u : 0u;
    }
}

// -------------------------------------------------------------------------
// Kernel 2: flat float4 gather. Blocks are region-pure (1024 float4/block;
// region sizes are exact multiples), so the region branch is per-block.
// PDL: address math runs while topk finishes; gridsync gates g_idx reads.
// -------------------------------------------------------------------------
__global__ __launch_bounds__(256)
void gather_kernel(const float4* __restrict__ hidden,
                   const float4* __restrict__ keys,
                   const float4* __restrict__ values,
                   float4*       __restrict__ out)
{
    const int bid = blockIdx.x;
    const int tid = threadIdx.x;

    if (bid < HBLK) {
        // hidden: rows of 512 float4 (8KB). Block covers e in [bid*1024, +1024)
        const long long e0 = (long long)bid * 1024 + tid;
        int k0 = (int)(e0 >> 9);                 // two consecutive k per block
        cudaGridDependencySynchronize();
        long long r0 = (long long)g_idx[k0] * 512;
        long long r1 = (long long)g_idx[k0 + (int)(((e0 & 511) + 256) >> 9) - (int)((e0 & 511) >> 9)];
        // simpler per-iteration form below; keep it branch-free:
        float4 v[4];
        #pragma unroll
        for (int it = 0; it < 4; ++it) {
            long long e = e0 + it * 256;
            int  k    = (int)(e >> 9);
            int  ln   = (int)(e & 511);
            v[it] = __ldcs(&hidden[(long long)g_idx[k] * 512 + ln]);
        }
        (void)r0; (void)r1;
        #pragma unroll
        for (int it = 0; it < 4; ++it) __stcs(&out[e0 + it * 256], v[it]);
    } else if (bid < HBLK + KBLK) {
        const long long t0 = (long long)(bid - HBLK) * 1024 + tid;
        cudaGridDependencySynchronize();
        float4 v[4];
        #pragma unroll
        for (int it = 0; it < 4; ++it) {
            long long t   = t0 + it * 256;
            long long row = t >> 5;
            int  k    = (int)(row & (KK - 1));
            long long lh  = row >> 12;
            v[it] = __ldcs(&keys[(lh * SS + g_idx[k]) * 32 + (int)(t & 31)]);
        }
        #pragma unroll
        for (int it = 0; it < 4; ++it) __stcs(&out[OFF_KEYS4 + t0 + it * 256], v[it]);
    } else {
        const long long t0 = (long long)(bid - HBLK - KBLK) * 1024 + tid;
        cudaGridDependencySynchronize();
        float4 v[4];
        #pragma unroll
        for (int it = 0; it < 4; ++it) {
            long long t   = t0 + it * 256;
            long long row = t >> 5;
            int  k    = (int)(row & (KK - 1));
            long long lh  = row >> 12;
            v[it] = __ldcs(&values[(lh * SS + g_idx[k]) * 32 + (int)(t & 31)]);
        }
        #pragma unroll
        for (int it = 0; it < 4; ++it) __stcs(&out[OFF_VALS4 + t0 + it * 256], v[it]);
    }
}

extern "C" void kernel_launch(void* const* d_in, const int* in_sizes, int n_in,
                              void* d_out, int out_size)
{
    const float* hidden = (const float*)d_in[0];   // [1,8192,2048] f32
    const float* scores = (const float*)d_in[1];   // [1,8192] f32
    const int*   amask  = (const int*)  d_in[2];   // [1,8192] i32
    const float* keys   = (const float*)d_in[3];   // [8,1,16,8192,128] f32
    const float* values = (const float*)d_in[4];   // [8,1,16,8192,128] f32
    float* out = (float*)d_out;

    topk_kernel<<<1, 1024>>>((const float4*)scores, amask, out);

    // Gather with Programmatic Dependent Launch
    int blocks = (int)(TOTAL4 / 1024);             // 34816
    cudaLaunchAttribute attrs[1];
    attrs[0].id = cudaLaunchAttributeProgrammaticStreamSerialization;
    attrs[0].val.programmaticStreamSerializationAllowed = 1;

    cudaLaunchConfig_t cfg = {};
    cfg.gridDim  = dim3((unsigned)blocks, 1, 1);
    cfg.blockDim = dim3(256, 1, 1);
    cfg.dynamicSmemBytes = 0;
    cfg.stream   = 0;
    cfg.attrs    = attrs;
    cfg.numAttrs = 1;

    cudaLaunchKernelEx(&cfg, gather_kernel,
                       (const float4*)hidden,
                       (const float4*)keys,
                       (const float4*)values,
                       (float4*)out);
}